// round 11
// baseline (speedup 1.0000x reference)
#include <cuda_runtime.h>
#include <cuda_fp16.h>
#include <cstdint>

#define M_DIM 4096
#define N_DIM 8192
#define K_DIM 2048

#define BM 128
#define BN 128
#define BK 64
#define NIT (K_DIM / BK)      // 32
#define NSTAGE 3
#define ROW_HALVES 64
#define A_HALVES (BM * ROW_HALVES)          // 8192
#define B_HALVES (BN * ROW_HALVES)          // 8192
#define STAGE_HALVES (A_HALVES + B_HALVES)  // 16384 (32 KB)
#define SMEM_BYTES (NSTAGE * STAGE_HALVES * 2)  // 98304 -> 2 CTAs/SM

// Static scratch (allocation-free rule): fp16 weights + fp16 activations
__device__ __align__(16) __half g_w[(size_t)N_DIM * K_DIM];  // 32 MB
__device__ __align__(16) __half g_x[(size_t)M_DIM * K_DIM];  // 16 MB

__constant__ float c_lut[16] = {
    -1.0f, -0.5f, -0.333333f, -0.2f, -0.142857f, -0.090909f, -0.076923f,
    0.0f, 0.076923f, 0.090909f, 0.142857f, 0.2f, 0.333333f, 0.5f, 1.0f, 0.0f};

// ---------------------------------------------------------------------------
// Fused prologue, 16 elements/thread (unchanged from R10 — measured neutral/ok)
// ---------------------------------------------------------------------------
#define W16B (N_DIM * (K_DIM / 16) / 256)   // 4096 blocks
#define X16B (M_DIM * (K_DIM / 16) / 256)   // 2048 blocks

__global__ __launch_bounds__(256) void prep_kernel(const float* __restrict__ x,
                                                   const int* __restrict__ gi,
                                                   const float* __restrict__ scale_p) {
    int b = blockIdx.x;
    if (b < W16B) {
        __shared__ float lut[16];
        if (threadIdx.x < 16) lut[threadIdx.x] = c_lut[threadIdx.x] * (*scale_p);
        __syncthreads();
        size_t t = (size_t)b * blockDim.x + threadIdx.x;
        const int4* gp = reinterpret_cast<const int4*>(gi) + t * 4;
        int4 v0 = gp[0];
        int4 v1 = gp[1];
        int4 v2 = gp[2];
        int4 v3 = gp[3];
        uint4 o0, o1;
        {
            __half2 h0 = __floats2half2_rn(lut[v0.x], lut[v0.y]);
            __half2 h1 = __floats2half2_rn(lut[v0.z], lut[v0.w]);
            __half2 h2 = __floats2half2_rn(lut[v1.x], lut[v1.y]);
            __half2 h3 = __floats2half2_rn(lut[v1.z], lut[v1.w]);
            o0.x = *reinterpret_cast<uint32_t*>(&h0);
            o0.y = *reinterpret_cast<uint32_t*>(&h1);
            o0.z = *reinterpret_cast<uint32_t*>(&h2);
            o0.w = *reinterpret_cast<uint32_t*>(&h3);
        }
        {
            __half2 h0 = __floats2half2_rn(lut[v2.x], lut[v2.y]);
            __half2 h1 = __floats2half2_rn(lut[v2.z], lut[v2.w]);
            __half2 h2 = __floats2half2_rn(lut[v3.x], lut[v3.y]);
            __half2 h3 = __floats2half2_rn(lut[v3.z], lut[v3.w]);
            o1.x = *reinterpret_cast<uint32_t*>(&h0);
            o1.y = *reinterpret_cast<uint32_t*>(&h1);
            o1.z = *reinterpret_cast<uint32_t*>(&h2);
            o1.w = *reinterpret_cast<uint32_t*>(&h3);
        }
        uint4* wp = reinterpret_cast<uint4*>(g_w + t * 16);
        wp[0] = o0;
        wp[1] = o1;
    } else {
        size_t t = (size_t)(b - W16B) * blockDim.x + threadIdx.x;
        const float4* xp = reinterpret_cast<const float4*>(x) + t * 4;
        float4 a0 = xp[0];
        float4 a1 = xp[1];
        float4 a2 = xp[2];
        float4 a3 = xp[3];
        uint4 o0, o1;
        {
            __half2 h0 = __floats2half2_rn(a0.x, a0.y);
            __half2 h1 = __floats2half2_rn(a0.z, a0.w);
            __half2 h2 = __floats2half2_rn(a1.x, a1.y);
            __half2 h3 = __floats2half2_rn(a1.z, a1.w);
            o0.x = *reinterpret_cast<uint32_t*>(&h0);
            o0.y = *reinterpret_cast<uint32_t*>(&h1);
            o0.z = *reinterpret_cast<uint32_t*>(&h2);
            o0.w = *reinterpret_cast<uint32_t*>(&h3);
        }
        {
            __half2 h0 = __floats2half2_rn(a2.x, a2.y);
            __half2 h1 = __floats2half2_rn(a2.z, a2.w);
            __half2 h2 = __floats2half2_rn(a3.x, a3.y);
            __half2 h3 = __floats2half2_rn(a3.z, a3.w);
            o1.x = *reinterpret_cast<uint32_t*>(&h0);
            o1.y = *reinterpret_cast<uint32_t*>(&h1);
            o1.z = *reinterpret_cast<uint32_t*>(&h2);
            o1.w = *reinterpret_cast<uint32_t*>(&h3);
        }
        uint4* wp = reinterpret_cast<uint4*>(g_x + t * 16);
        wp[0] = o0;
        wp[1] = o1;
    }
}

// ---------------------------------------------------------------------------
// helpers
// ---------------------------------------------------------------------------
__device__ __forceinline__ void cp16(__half* dst, const __half* src) {
    uint32_t d = (uint32_t)__cvta_generic_to_shared(dst);
    asm volatile("cp.async.cg.shared.global [%0], [%1], 16;\n" :: "r"(d), "l"(src));
}

__device__ __forceinline__ void ldsm4(uint32_t* r, const __half* p) {
    uint32_t a = (uint32_t)__cvta_generic_to_shared(p);
    asm volatile("ldmatrix.sync.aligned.m8n8.x4.shared.b16 {%0,%1,%2,%3}, [%4];\n"
                 : "=r"(r[0]), "=r"(r[1]), "=r"(r[2]), "=r"(r[3]) : "r"(a));
}

__device__ __forceinline__ void mma16816(float* c, const uint32_t* a, const uint32_t* b) {
    asm volatile(
        "mma.sync.aligned.m16n8k16.row.col.f32.f16.f16.f32 "
        "{%0,%1,%2,%3}, {%4,%5,%6,%7}, {%8,%9}, {%0,%1,%2,%3};\n"
        : "+f"(c[0]), "+f"(c[1]), "+f"(c[2]), "+f"(c[3])
        : "r"(a[0]), "r"(a[1]), "r"(a[2]), "r"(a[3]), "r"(b[0]), "r"(b[1]));
}

// swizzled address: row (128B rows), 16B-chunk index. phys chunk = chunk ^ (row & 7)
__device__ __forceinline__ const __half* swz(const __half* base, int row, int chunk) {
    return base + row * ROW_HALVES + ((chunk ^ (row & 7)) << 3);
}
__device__ __forceinline__ __half* swzw(__half* base, int row, int chunk) {
    return base + row * ROW_HALVES + ((chunk ^ (row & 7)) << 3);
}

// ---------------------------------------------------------------------------
// GEMM: out[M,N] = g_x[M,K] @ g_w[N,K]^T
// Discriminating config: CTA 128x128x64, 128 threads, 4 warps (2M x 2N),
// warp tile 64x64 -> 128 B LDSM per MMA (vs 192 before). 2 CTAs/SM,
// 3-stage cp.async, XOR swizzle, fp32 acc, intra-iter fragment
// double-buffering. ~210 regs/thread, no spill at 128 threads.
// ---------------------------------------------------------------------------
__global__ __launch_bounds__(128, 2) void gemm_kernel(float* __restrict__ out) {
    extern __shared__ __half sm[];

    const int tid = threadIdx.x;
    const int warp = tid >> 5;
    const int lane = tid & 31;
    const int wm = warp >> 1;  // 0..1 : 64-row slice
    const int wn = warp & 1;   // 0..1 : 64-col slice
    const int m0 = blockIdx.y * BM;
    const int n0 = blockIdx.x * BN;

    const int crow = tid;      // one row per thread, all 8 chunks (A and B)

    // fragment coordinates (fixed per thread)
    const int arow0 = wm * 64 + (lane & 15);
    const int achk = lane >> 4;                                   // 0..1
    const int brow = wn * 64 + (lane & 7) + ((lane >> 4) & 1) * 8;
    const int bchk = (lane >> 3) & 1;                             // 0..1

    float acc[4][8][4];
#pragma unroll
    for (int i = 0; i < 4; i++)
#pragma unroll
        for (int j = 0; j < 8; j++)
#pragma unroll
            for (int k = 0; k < 4; k++) acc[i][j][k] = 0.0f;

    auto load_stage = [&](int s, int k0) {
        __half* a = sm + s * STAGE_HALVES;
        __half* b = a + A_HALVES;
        const __half* ga = g_x + (size_t)(m0 + crow) * K_DIM + k0;
        const __half* gb = g_w + (size_t)(n0 + crow) * K_DIM + k0;
#pragma unroll
        for (int j = 0; j < 8; j++) {
            cp16(swzw(a, crow, j), ga + j * 8);
            cp16(swzw(b, crow, j), gb + j * 8);
        }
        asm volatile("cp.async.commit_group;\n");
    };

    load_stage(0, 0);
    load_stage(1, BK);

    uint32_t af0[4][4], af1[4][4];
    uint32_t bf0[8][2], bf1[8][2];

#define LOAD_FRAGS(AF, BF, a_s, b_s, kc)                                         \
    do {                                                                         \
        _Pragma("unroll")                                                        \
        for (int mt = 0; mt < 4; mt++)                                           \
            ldsm4(AF[mt], swz(a_s, arow0 + mt * 16, (kc) + achk));               \
        _Pragma("unroll")                                                        \
        for (int np = 0; np < 4; np++) {                                         \
            uint32_t r_[4];                                                      \
            ldsm4(r_, swz(b_s, brow + np * 16, (kc) + bchk));                    \
            BF[np * 2][0] = r_[0]; BF[np * 2][1] = r_[1];                        \
            BF[np * 2 + 1][0] = r_[2]; BF[np * 2 + 1][1] = r_[3];                \
        }                                                                        \
    } while (0)

#define MMA_STEP(AF, BF)                                                         \
    do {                                                                         \
        _Pragma("unroll")                                                        \
        for (int mt = 0; mt < 4; mt++)                                           \
            _Pragma("unroll")                                                    \
            for (int nt = 0; nt < 8; nt++)                                       \
                mma16816(acc[mt][nt], AF[mt], BF[nt]);                           \
    } while (0)

    for (int it = 0; it < NIT; ++it) {
        asm volatile("cp.async.wait_group 1;\n");
        __syncthreads();

        if (it + 2 < NIT) load_stage((it + 2) % NSTAGE, (it + 2) * BK);

        const __half* a_s = sm + (it % NSTAGE) * STAGE_HALVES;
        const __half* b_s = a_s + A_HALVES;

        LOAD_FRAGS(af0, bf0, a_s, b_s, 0);
        LOAD_FRAGS(af1, bf1, a_s, b_s, 2);
        MMA_STEP(af0, bf0);
        LOAD_FRAGS(af0, bf0, a_s, b_s, 4);
        MMA_STEP(af1, bf1);
        LOAD_FRAGS(af1, bf1, a_s, b_s, 6);
        MMA_STEP(af0, bf0);
        MMA_STEP(af1, bf1);
    }

    // epilogue: direct fp32 stores
#pragma unroll
    for (int mt = 0; mt < 4; mt++) {
#pragma unroll
        for (int nt = 0; nt < 8; nt++) {
            int row = m0 + wm * 64 + mt * 16 + (lane >> 2);
            int col = n0 + wn * 64 + nt * 8 + (lane & 3) * 2;
            float2 v0 = make_float2(acc[mt][nt][0], acc[mt][nt][1]);
            float2 v1 = make_float2(acc[mt][nt][2], acc[mt][nt][3]);
            *reinterpret_cast<float2*>(out + (size_t)row * N_DIM + col) = v0;
            *reinterpret_cast<float2*>(out + (size_t)(row + 8) * N_DIM + col) = v1;
        }
    }
}

// ---------------------------------------------------------------------------
// kernel_launch
// ---------------------------------------------------------------------------
extern "C" void kernel_launch(void* const* d_in, const int* in_sizes, int n_in,
                              void* d_out, int out_size) {
    const float* x = (const float*)d_in[0];
    const int* gi = (const int*)d_in[1];
    const float* scale = (const float*)d_in[2];
    float* out = (float*)d_out;

    prep_kernel<<<W16B + X16B, 256>>>(x, gi, scale);

    cudaFuncSetAttribute(gemm_kernel, cudaFuncAttributeMaxDynamicSharedMemorySize, SMEM_BYTES);
    dim3 grid(N_DIM / BN, M_DIM / BM);  // (64, 32)
    gemm_kernel<<<grid, 128, SMEM_BYTES>>>(out);
}

// round 12
// speedup vs baseline: 1.4227x; 1.4227x over previous
#include <cuda_runtime.h>
#include <cuda_fp16.h>
#include <cstdint>

#define M_DIM 4096
#define N_DIM 8192
#define K_DIM 2048

#define BM 128
#define BN 128
#define BK 64
#define NIT (K_DIM / BK)      // 32
#define NSTAGE 3
#define ROW_HALVES 64
#define A_HALVES (BM * ROW_HALVES)          // 8192
#define B_HALVES (BN * ROW_HALVES)          // 8192
#define STAGE_HALVES (A_HALVES + B_HALVES)  // 16384 (32 KB)
#define SMEM_BYTES (NSTAGE * STAGE_HALVES * 2)  // 98304 -> 2 CTAs/SM

// Static scratch (allocation-free rule): fp16 weights + fp16 activations
__device__ __align__(16) __half g_w[(size_t)N_DIM * K_DIM];  // 32 MB
__device__ __align__(16) __half g_x[(size_t)M_DIM * K_DIM];  // 16 MB

__constant__ float c_lut[16] = {
    -1.0f, -0.5f, -0.333333f, -0.2f, -0.142857f, -0.090909f, -0.076923f,
    0.0f, 0.076923f, 0.090909f, 0.142857f, 0.2f, 0.333333f, 0.5f, 1.0f, 0.0f};

// ---------------------------------------------------------------------------
// Fused prologue, 16 elements/thread.
// W path uses a 256-entry PAIR lut (__half2 for an index pair) -> 32 LDS
// lookups per thread instead of 64, zero float->half converts in hot path.
// ---------------------------------------------------------------------------
#define W16B (N_DIM * (K_DIM / 16) / 256)   // 4096 blocks
#define X16B (M_DIM * (K_DIM / 16) / 256)   // 2048 blocks

__global__ __launch_bounds__(256) void prep_kernel(const float* __restrict__ x,
                                                   const int* __restrict__ gi,
                                                   const float* __restrict__ scale_p) {
    int b = blockIdx.x;
    if (b < W16B) {
        __shared__ __half2 lut2[256];
        {
            float s = *scale_p;
            int i = threadIdx.x >> 4, j = threadIdx.x & 15;
            lut2[threadIdx.x] = __floats2half2_rn(c_lut[i] * s, c_lut[j] * s);
        }
        __syncthreads();
        size_t t = (size_t)b * blockDim.x + threadIdx.x;
        const int4* gp = reinterpret_cast<const int4*>(gi) + t * 4;
        int4 v0 = gp[0];
        int4 v1 = gp[1];
        int4 v2 = gp[2];
        int4 v3 = gp[3];
        uint4 o0, o1;
        o0.x = *reinterpret_cast<const uint32_t*>(&lut2[(v0.x << 4) | v0.y]);
        o0.y = *reinterpret_cast<const uint32_t*>(&lut2[(v0.z << 4) | v0.w]);
        o0.z = *reinterpret_cast<const uint32_t*>(&lut2[(v1.x << 4) | v1.y]);
        o0.w = *reinterpret_cast<const uint32_t*>(&lut2[(v1.z << 4) | v1.w]);
        o1.x = *reinterpret_cast<const uint32_t*>(&lut2[(v2.x << 4) | v2.y]);
        o1.y = *reinterpret_cast<const uint32_t*>(&lut2[(v2.z << 4) | v2.w]);
        o1.z = *reinterpret_cast<const uint32_t*>(&lut2[(v3.x << 4) | v3.y]);
        o1.w = *reinterpret_cast<const uint32_t*>(&lut2[(v3.z << 4) | v3.w]);
        uint4* wp = reinterpret_cast<uint4*>(g_w + t * 16);
        wp[0] = o0;
        wp[1] = o1;
    } else {
        size_t t = (size_t)(b - W16B) * blockDim.x + threadIdx.x;
        const float4* xp = reinterpret_cast<const float4*>(x) + t * 4;
        float4 a0 = xp[0];
        float4 a1 = xp[1];
        float4 a2 = xp[2];
        float4 a3 = xp[3];
        uint4 o0, o1;
        {
            __half2 h0 = __floats2half2_rn(a0.x, a0.y);
            __half2 h1 = __floats2half2_rn(a0.z, a0.w);
            __half2 h2 = __floats2half2_rn(a1.x, a1.y);
            __half2 h3 = __floats2half2_rn(a1.z, a1.w);
            o0.x = *reinterpret_cast<uint32_t*>(&h0);
            o0.y = *reinterpret_cast<uint32_t*>(&h1);
            o0.z = *reinterpret_cast<uint32_t*>(&h2);
            o0.w = *reinterpret_cast<uint32_t*>(&h3);
        }
        {
            __half2 h0 = __floats2half2_rn(a2.x, a2.y);
            __half2 h1 = __floats2half2_rn(a2.z, a2.w);
            __half2 h2 = __floats2half2_rn(a3.x, a3.y);
            __half2 h3 = __floats2half2_rn(a3.z, a3.w);
            o1.x = *reinterpret_cast<uint32_t*>(&h0);
            o1.y = *reinterpret_cast<uint32_t*>(&h1);
            o1.z = *reinterpret_cast<uint32_t*>(&h2);
            o1.w = *reinterpret_cast<uint32_t*>(&h3);
        }
        uint4* wp = reinterpret_cast<uint4*>(g_x + t * 16);
        wp[0] = o0;
        wp[1] = o1;
    }
}

// ---------------------------------------------------------------------------
// helpers
// ---------------------------------------------------------------------------
__device__ __forceinline__ void cp16(__half* dst, const __half* src) {
    uint32_t d = (uint32_t)__cvta_generic_to_shared(dst);
    asm volatile("cp.async.cg.shared.global [%0], [%1], 16;\n" :: "r"(d), "l"(src));
}

__device__ __forceinline__ void ldsm4(uint32_t* r, const __half* p) {
    uint32_t a = (uint32_t)__cvta_generic_to_shared(p);
    asm volatile("ldmatrix.sync.aligned.m8n8.x4.shared.b16 {%0,%1,%2,%3}, [%4];\n"
                 : "=r"(r[0]), "=r"(r[1]), "=r"(r[2]), "=r"(r[3]) : "r"(a));
}

__device__ __forceinline__ void mma16816(float* c, const uint32_t* a, const uint32_t* b) {
    asm volatile(
        "mma.sync.aligned.m16n8k16.row.col.f32.f16.f16.f32 "
        "{%0,%1,%2,%3}, {%4,%5,%6,%7}, {%8,%9}, {%0,%1,%2,%3};\n"
        : "+f"(c[0]), "+f"(c[1]), "+f"(c[2]), "+f"(c[3])
        : "r"(a[0]), "r"(a[1]), "r"(a[2]), "r"(a[3]), "r"(b[0]), "r"(b[1]));
}

// swizzled address: row (128B rows), 16B-chunk index. phys chunk = chunk ^ (row & 7)
__device__ __forceinline__ const __half* swz(const __half* base, int row, int chunk) {
    return base + row * ROW_HALVES + ((chunk ^ (row & 7)) << 3);
}
__device__ __forceinline__ __half* swzw(__half* base, int row, int chunk) {
    return base + row * ROW_HALVES + ((chunk ^ (row & 7)) << 3);
}

// ---------------------------------------------------------------------------
// GEMM: out[M,N] = g_x[M,K] @ g_w[N,K]^T   (byte-identical to R9/R10 best)
// CTA 128x128x64, 8 warps (4M x 2N), warp tile 32x64, 3-stage cp.async,
// XOR swizzle, 2 CTAs/SM, fp32 accumulators, intra-iter fragment
// double-buffering. Measured at the mma.sync issue-rate floor (~497 us).
// ---------------------------------------------------------------------------
__global__ __launch_bounds__(256, 2) void gemm_kernel(float* __restrict__ out) {
    extern __shared__ __half sm[];

    const int tid = threadIdx.x;
    const int warp = tid >> 5;
    const int lane = tid & 31;
    const int wm = warp & 3;   // 0..3 : 32-row slice
    const int wn = warp >> 2;  // 0..1 : 64-col slice
    const int m0 = blockIdx.y * BM;
    const int n0 = blockIdx.x * BN;

    const int crow = tid >> 1;           // 0..127
    const int cchk = (tid & 1) * 4;      // chunks 0-3 or 4-7

    const int arow0 = wm * 32 + (lane & 15);
    const int achk = lane >> 4;                                   // 0..1
    const int brow = wn * 64 + (lane & 7) + ((lane >> 4) & 1) * 8;
    const int bchk = (lane >> 3) & 1;                             // 0..1

    float acc[2][8][4];
#pragma unroll
    for (int i = 0; i < 2; i++)
#pragma unroll
        for (int j = 0; j < 8; j++)
#pragma unroll
            for (int k = 0; k < 4; k++) acc[i][j][k] = 0.0f;

    auto load_stage = [&](int s, int k0) {
        __half* a = sm + s * STAGE_HALVES;
        __half* b = a + A_HALVES;
        const __half* ga = g_x + (size_t)(m0 + crow) * K_DIM + k0 + cchk * 8;
        const __half* gb = g_w + (size_t)(n0 + crow) * K_DIM + k0 + cchk * 8;
#pragma unroll
        for (int j = 0; j < 4; j++) {
            cp16(swzw(a, crow, cchk + j), ga + j * 8);
            cp16(swzw(b, crow, cchk + j), gb + j * 8);
        }
        asm volatile("cp.async.commit_group;\n");
    };

    load_stage(0, 0);
    load_stage(1, BK);

    uint32_t af0[2][4], af1[2][4];
    uint32_t bf0[8][2], bf1[8][2];

#define LOAD_FRAGS(AF, BF, a_s, b_s, kc)                                         \
    do {                                                                         \
        _Pragma("unroll")                                                        \
        for (int mt = 0; mt < 2; mt++)                                           \
            ldsm4(AF[mt], swz(a_s, arow0 + mt * 16, (kc) + achk));               \
        _Pragma("unroll")                                                        \
        for (int np = 0; np < 4; np++) {                                         \
            uint32_t r_[4];                                                      \
            ldsm4(r_, swz(b_s, brow + np * 16, (kc) + bchk));                    \
            BF[np * 2][0] = r_[0]; BF[np * 2][1] = r_[1];                        \
            BF[np * 2 + 1][0] = r_[2]; BF[np * 2 + 1][1] = r_[3];                \
        }                                                                        \
    } while (0)

#define MMA_STEP(AF, BF)                                                         \
    do {                                                                         \
        _Pragma("unroll")                                                        \
        for (int mt = 0; mt < 2; mt++)                                           \
            _Pragma("unroll")                                                    \
            for (int nt = 0; nt < 8; nt++)                                       \
                mma16816(acc[mt][nt], AF[mt], BF[nt]);                           \
    } while (0)

    for (int it = 0; it < NIT; ++it) {
        asm volatile("cp.async.wait_group 1;\n");
        __syncthreads();

        if (it + 2 < NIT) load_stage((it + 2) % NSTAGE, (it + 2) * BK);

        const __half* a_s = sm + (it % NSTAGE) * STAGE_HALVES;
        const __half* b_s = a_s + A_HALVES;

        LOAD_FRAGS(af0, bf0, a_s, b_s, 0);
        LOAD_FRAGS(af1, bf1, a_s, b_s, 2);
        MMA_STEP(af0, bf0);
        LOAD_FRAGS(af0, bf0, a_s, b_s, 4);
        MMA_STEP(af1, bf1);
        LOAD_FRAGS(af1, bf1, a_s, b_s, 6);
        MMA_STEP(af0, bf0);
        MMA_STEP(af1, bf1);
    }

    // epilogue: direct fp32 stores
#pragma unroll
    for (int mt = 0; mt < 2; mt++) {
#pragma unroll
        for (int nt = 0; nt < 8; nt++) {
            int row = m0 + wm * 32 + mt * 16 + (lane >> 2);
            int col = n0 + wn * 64 + nt * 8 + (lane & 3) * 2;
            float2 v0 = make_float2(acc[mt][nt][0], acc[mt][nt][1]);
            float2 v1 = make_float2(acc[mt][nt][2], acc[mt][nt][3]);
            *reinterpret_cast<float2*>(out + (size_t)row * N_DIM + col) = v0;
            *reinterpret_cast<float2*>(out + (size_t)(row + 8) * N_DIM + col) = v1;
        }
    }
}

// ---------------------------------------------------------------------------
// kernel_launch
// ---------------------------------------------------------------------------
extern "C" void kernel_launch(void* const* d_in, const int* in_sizes, int n_in,
                              void* d_out, int out_size) {
    const float* x = (const float*)d_in[0];
    const int* gi = (const int*)d_in[1];
    const float* scale = (const float*)d_in[2];
    float* out = (float*)d_out;

    prep_kernel<<<W16B + X16B, 256>>>(x, gi, scale);

    cudaFuncSetAttribute(gemm_kernel, cudaFuncAttributeMaxDynamicSharedMemorySize, SMEM_BYTES);
    dim3 grid(N_DIM / BN, M_DIM / BM);  // (64, 32)
    gemm_kernel<<<grid, 256, SMEM_BYTES>>>(out);
}

// round 13
// speedup vs baseline: 1.4238x; 1.0008x over previous
#include <cuda_runtime.h>
#include <cuda_fp16.h>
#include <cstdint>

#define M_DIM 4096
#define N_DIM 8192
#define K_DIM 2048

#define BM 128
#define BN 128
#define BK 64
#define NIT (K_DIM / BK)      // 32
#define NSTAGE 3
#define ROW_HALVES 64
#define A_HALVES (BM * ROW_HALVES)          // 8192
#define B_HALVES (BN * ROW_HALVES)          // 8192
#define STAGE_HALVES (A_HALVES + B_HALVES)  // 16384 (32 KB)
#define SMEM_BYTES (NSTAGE * STAGE_HALVES * 2)  // 98304 -> 2 CTAs/SM

// Static scratch (allocation-free rule): fp16 weights + fp16 activations
__device__ __align__(16) __half g_w[(size_t)N_DIM * K_DIM];  // 32 MB
__device__ __align__(16) __half g_x[(size_t)M_DIM * K_DIM];  // 16 MB

__constant__ float c_lut[16] = {
    -1.0f, -0.5f, -0.333333f, -0.2f, -0.142857f, -0.090909f, -0.076923f,
    0.0f, 0.076923f, 0.090909f, 0.142857f, 0.2f, 0.333333f, 0.5f, 1.0f, 0.0f};

// ---------------------------------------------------------------------------
// Fused prologue, 16 elements/thread. W path: 256-entry PAIR lut (__half2 per
// index pair) -> 32 LDS lookups/thread, no float->half cvt in hot path.
// ---------------------------------------------------------------------------
#define W16B (N_DIM * (K_DIM / 16) / 256)   // 4096 blocks
#define X16B (M_DIM * (K_DIM / 16) / 256)   // 2048 blocks

__global__ __launch_bounds__(256) void prep_kernel(const float* __restrict__ x,
                                                   const int* __restrict__ gi,
                                                   const float* __restrict__ scale_p) {
    int b = blockIdx.x;
    if (b < W16B) {
        __shared__ __half2 lut2[256];
        {
            float s = *scale_p;
            int i = threadIdx.x >> 4, j = threadIdx.x & 15;
            lut2[threadIdx.x] = __floats2half2_rn(c_lut[i] * s, c_lut[j] * s);
        }
        __syncthreads();
        size_t t = (size_t)b * blockDim.x + threadIdx.x;
        const int4* gp = reinterpret_cast<const int4*>(gi) + t * 4;
        int4 v0 = gp[0];
        int4 v1 = gp[1];
        int4 v2 = gp[2];
        int4 v3 = gp[3];
        uint4 o0, o1;
        o0.x = *reinterpret_cast<const uint32_t*>(&lut2[(v0.x << 4) | v0.y]);
        o0.y = *reinterpret_cast<const uint32_t*>(&lut2[(v0.z << 4) | v0.w]);
        o0.z = *reinterpret_cast<const uint32_t*>(&lut2[(v1.x << 4) | v1.y]);
        o0.w = *reinterpret_cast<const uint32_t*>(&lut2[(v1.z << 4) | v1.w]);
        o1.x = *reinterpret_cast<const uint32_t*>(&lut2[(v2.x << 4) | v2.y]);
        o1.y = *reinterpret_cast<const uint32_t*>(&lut2[(v2.z << 4) | v2.w]);
        o1.z = *reinterpret_cast<const uint32_t*>(&lut2[(v3.x << 4) | v3.y]);
        o1.w = *reinterpret_cast<const uint32_t*>(&lut2[(v3.z << 4) | v3.w]);
        uint4* wp = reinterpret_cast<uint4*>(g_w + t * 16);
        wp[0] = o0;
        wp[1] = o1;
    } else {
        size_t t = (size_t)(b - W16B) * blockDim.x + threadIdx.x;
        const float4* xp = reinterpret_cast<const float4*>(x) + t * 4;
        float4 a0 = xp[0];
        float4 a1 = xp[1];
        float4 a2 = xp[2];
        float4 a3 = xp[3];
        uint4 o0, o1;
        {
            __half2 h0 = __floats2half2_rn(a0.x, a0.y);
            __half2 h1 = __floats2half2_rn(a0.z, a0.w);
            __half2 h2 = __floats2half2_rn(a1.x, a1.y);
            __half2 h3 = __floats2half2_rn(a1.z, a1.w);
            o0.x = *reinterpret_cast<uint32_t*>(&h0);
            o0.y = *reinterpret_cast<uint32_t*>(&h1);
            o0.z = *reinterpret_cast<uint32_t*>(&h2);
            o0.w = *reinterpret_cast<uint32_t*>(&h3);
        }
        {
            __half2 h0 = __floats2half2_rn(a2.x, a2.y);
            __half2 h1 = __floats2half2_rn(a2.z, a2.w);
            __half2 h2 = __floats2half2_rn(a3.x, a3.y);
            __half2 h3 = __floats2half2_rn(a3.z, a3.w);
            o1.x = *reinterpret_cast<uint32_t*>(&h0);
            o1.y = *reinterpret_cast<uint32_t*>(&h1);
            o1.z = *reinterpret_cast<uint32_t*>(&h2);
            o1.w = *reinterpret_cast<uint32_t*>(&h3);
        }
        uint4* wp = reinterpret_cast<uint4*>(g_x + t * 16);
        wp[0] = o0;
        wp[1] = o1;
    }
}

// ---------------------------------------------------------------------------
// helpers
// ---------------------------------------------------------------------------
__device__ __forceinline__ void cp16(__half* dst, const __half* src) {
    uint32_t d = (uint32_t)__cvta_generic_to_shared(dst);
    asm volatile("cp.async.cg.shared.global [%0], [%1], 16;\n" :: "r"(d), "l"(src));
}

__device__ __forceinline__ void ldsm4(uint32_t* r, const __half* p) {
    uint32_t a = (uint32_t)__cvta_generic_to_shared(p);
    asm volatile("ldmatrix.sync.aligned.m8n8.x4.shared.b16 {%0,%1,%2,%3}, [%4];\n"
                 : "=r"(r[0]), "=r"(r[1]), "=r"(r[2]), "=r"(r[3]) : "r"(a));
}

__device__ __forceinline__ void mma16816(float* c, const uint32_t* a, const uint32_t* b) {
    asm volatile(
        "mma.sync.aligned.m16n8k16.row.col.f32.f16.f16.f32 "
        "{%0,%1,%2,%3}, {%4,%5,%6,%7}, {%8,%9}, {%0,%1,%2,%3};\n"
        : "+f"(c[0]), "+f"(c[1]), "+f"(c[2]), "+f"(c[3])
        : "r"(a[0]), "r"(a[1]), "r"(a[2]), "r"(a[3]), "r"(b[0]), "r"(b[1]));
}

// streaming store: output is write-once, never re-read -> don't pollute L2
__device__ __forceinline__ void stcs2(float* p, float2 v) {
    asm volatile("st.global.cs.v2.f32 [%0], {%1, %2};\n" :: "l"(p), "f"(v.x), "f"(v.y) : "memory");
}

// swizzled address: row (128B rows), 16B-chunk index. phys chunk = chunk ^ (row & 7)
__device__ __forceinline__ const __half* swz(const __half* base, int row, int chunk) {
    return base + row * ROW_HALVES + ((chunk ^ (row & 7)) << 3);
}
__device__ __forceinline__ __half* swzw(__half* base, int row, int chunk) {
    return base + row * ROW_HALVES + ((chunk ^ (row & 7)) << 3);
}

// ---------------------------------------------------------------------------
// GEMM: out[M,N] = g_x[M,K] @ g_w[N,K]^T
// CTA 128x128x64, 8 warps (4M x 2N), warp tile 32x64, 3-stage cp.async,
// XOR swizzle, 2 CTAs/SM, fp32 accumulators, intra-iter fragment
// double-buffering. At the measured mma.sync pipe floor (512 MAC/cyc/SM).
// ---------------------------------------------------------------------------
__global__ __launch_bounds__(256, 2) void gemm_kernel(float* __restrict__ out) {
    extern __shared__ __half sm[];

    const int tid = threadIdx.x;
    const int warp = tid >> 5;
    const int lane = tid & 31;
    const int wm = warp & 3;   // 0..3 : 32-row slice
    const int wn = warp >> 2;  // 0..1 : 64-col slice
    const int m0 = blockIdx.y * BM;
    const int n0 = blockIdx.x * BN;

    const int crow = tid >> 1;           // 0..127
    const int cchk = (tid & 1) * 4;      // chunks 0-3 or 4-7

    const int arow0 = wm * 32 + (lane & 15);
    const int achk = lane >> 4;                                   // 0..1
    const int brow = wn * 64 + (lane & 7) + ((lane >> 4) & 1) * 8;
    const int bchk = (lane >> 3) & 1;                             // 0..1

    float acc[2][8][4];
#pragma unroll
    for (int i = 0; i < 2; i++)
#pragma unroll
        for (int j = 0; j < 8; j++)
#pragma unroll
            for (int k = 0; k < 4; k++) acc[i][j][k] = 0.0f;

    auto load_stage = [&](int s, int k0) {
        __half* a = sm + s * STAGE_HALVES;
        __half* b = a + A_HALVES;
        const __half* ga = g_x + (size_t)(m0 + crow) * K_DIM + k0 + cchk * 8;
        const __half* gb = g_w + (size_t)(n0 + crow) * K_DIM + k0 + cchk * 8;
#pragma unroll
        for (int j = 0; j < 4; j++) {
            cp16(swzw(a, crow, cchk + j), ga + j * 8);
            cp16(swzw(b, crow, cchk + j), gb + j * 8);
        }
        asm volatile("cp.async.commit_group;\n");
    };

    load_stage(0, 0);
    load_stage(1, BK);

    uint32_t af0[2][4], af1[2][4];
    uint32_t bf0[8][2], bf1[8][2];

#define LOAD_FRAGS(AF, BF, a_s, b_s, kc)                                         \
    do {                                                                         \
        _Pragma("unroll")                                                        \
        for (int mt = 0; mt < 2; mt++)                                           \
            ldsm4(AF[mt], swz(a_s, arow0 + mt * 16, (kc) + achk));               \
        _Pragma("unroll")                                                        \
        for (int np = 0; np < 4; np++) {                                         \
            uint32_t r_[4];                                                      \
            ldsm4(r_, swz(b_s, brow + np * 16, (kc) + bchk));                    \
            BF[np * 2][0] = r_[0]; BF[np * 2][1] = r_[1];                        \
            BF[np * 2 + 1][0] = r_[2]; BF[np * 2 + 1][1] = r_[3];                \
        }                                                                        \
    } while (0)

#define MMA_STEP(AF, BF)                                                         \
    do {                                                                         \
        _Pragma("unroll")                                                        \
        for (int mt = 0; mt < 2; mt++)                                           \
            _Pragma("unroll")                                                    \
            for (int nt = 0; nt < 8; nt++)                                       \
                mma16816(acc[mt][nt], AF[mt], BF[nt]);                           \
    } while (0)

    for (int it = 0; it < NIT; ++it) {
        asm volatile("cp.async.wait_group 1;\n");
        __syncthreads();

        if (it + 2 < NIT) load_stage((it + 2) % NSTAGE, (it + 2) * BK);

        const __half* a_s = sm + (it % NSTAGE) * STAGE_HALVES;
        const __half* b_s = a_s + A_HALVES;

        LOAD_FRAGS(af0, bf0, a_s, b_s, 0);
        LOAD_FRAGS(af1, bf1, a_s, b_s, 2);
        MMA_STEP(af0, bf0);
        LOAD_FRAGS(af0, bf0, a_s, b_s, 4);
        MMA_STEP(af1, bf1);
        LOAD_FRAGS(af1, bf1, a_s, b_s, 6);
        MMA_STEP(af0, bf0);
        MMA_STEP(af1, bf1);
    }

    // epilogue: streaming fp32 stores (write-once output, keep w/x hot in L2)
#pragma unroll
    for (int mt = 0; mt < 2; mt++) {
#pragma unroll
        for (int nt = 0; nt < 8; nt++) {
            int row = m0 + wm * 32 + mt * 16 + (lane >> 2);
            int col = n0 + wn * 64 + nt * 8 + (lane & 3) * 2;
            stcs2(out + (size_t)row * N_DIM + col,
                  make_float2(acc[mt][nt][0], acc[mt][nt][1]));
            stcs2(out + (size_t)(row + 8) * N_DIM + col,
                  make_float2(acc[mt][nt][2], acc[mt][nt][3]));
        }
    }
}

// ---------------------------------------------------------------------------
// kernel_launch
// ---------------------------------------------------------------------------
extern "C" void kernel_launch(void* const* d_in, const int* in_sizes, int n_in,
                              void* d_out, int out_size) {
    const float* x = (const float*)d_in[0];
    const int* gi = (const int*)d_in[1];
    const float* scale = (const float*)d_in[2];
    float* out = (float*)d_out;

    prep_kernel<<<W16B + X16B, 256>>>(x, gi, scale);

    cudaFuncSetAttribute(gemm_kernel, cudaFuncAttributeMaxDynamicSharedMemorySize, SMEM_BYTES);
    dim3 grid(N_DIM / BN, M_DIM / BM);  // (64, 32)
    gemm_kernel<<<grid, 256, SMEM_BYTES>>>(out);
}